// round 1
// baseline (speedup 1.0000x reference)
#include <cuda_runtime.h>
#include <math.h>

#define N_NODES 150000
#define N_ETYPES 1000
#define B_EDGES 16384
#define H 128
#define D_IN 50          // 2 cont + 3*16 cat
#define NT 16            // nodes per block tile (150000 / 16 = 9375 exact)
#define P_IN 336         // 2*128 + 32 + 2*16 + 16
#define P_HID 64

__device__ __forceinline__ float sigmoidf_(float x) {
    return 1.0f / (1.0f + expf(-x));
}

// ---------------------------------------------------------------------------
// Kernel A: fused feature build + 4-gate LSTM update for all nodes.
// blockDim = 128 (thread = output column h), each block handles NT nodes.
// z[g][n][h] = b_gate[g][h] + sum_d x[n][d]*Wx[g][d][h] + sum_k hprev[n][k]*Wh[g][k][h]
// ---------------------------------------------------------------------------
__global__ void __launch_bounds__(128) node_update_kernel(
    const float* __restrict__ node_cont,     // (N,2)
    const int*   __restrict__ ncat_codes,    // (3,N)
    const float* __restrict__ ncat_emb,      // (3,64,16)
    const float* __restrict__ h_prev,        // (N,128)
    const float* __restrict__ c_prev,        // (N,128)
    const float* __restrict__ Wx,            // (4,50,128)
    const float* __restrict__ Wh,            // (4,128,128)
    const float* __restrict__ b_gate,        // (4,128)
    const float* __restrict__ w_c,           // (3,128)
    float* __restrict__ h_new,               // (N,128)
    float* __restrict__ c_new)               // (N,128)
{
    __shared__ float xs[NT][D_IN];
    __shared__ float hs[NT][H];

    const int tid = threadIdx.x;
    const int n0  = blockIdx.x * NT;

    // ---- stage x features for the node tile (cont + 3 gathered cat embeds)
    for (int idx = tid; idx < NT * D_IN; idx += 128) {
        int n = idx / D_IN;
        int d = idx - n * D_IN;
        int node = n0 + n;
        float v;
        if (d < 2) {
            v = node_cont[node * 2 + d];
        } else {
            int dd = d - 2;
            int j = dd >> 4;          // which cat field (0..2)
            int k = dd & 15;          // dim within embedding
            int code = ncat_codes[j * N_NODES + node];
            v = ncat_emb[(j * 64 + code) * 16 + k];
        }
        xs[n][d] = v;
    }
    // ---- stage h_prev tile
    for (int idx = tid; idx < NT * H; idx += 128) {
        int n = idx >> 7;
        int k = idx & 127;
        hs[n][k] = h_prev[(size_t)(n0 + n) * H + k];
    }
    __syncthreads();

    float acc0[NT], acc1[NT], acc2[NT], acc3[NT];
    {
        float bg0 = b_gate[0 * H + tid];
        float bg1 = b_gate[1 * H + tid];
        float bg2 = b_gate[2 * H + tid];
        float bg3 = b_gate[3 * H + tid];
        #pragma unroll
        for (int n = 0; n < NT; ++n) {
            acc0[n] = bg0; acc1[n] = bg1; acc2[n] = bg2; acc3[n] = bg3;
        }
    }

    // ---- x @ Wx (50 steps)
    #pragma unroll 2
    for (int d = 0; d < D_IN; ++d) {
        float w0 = Wx[(0 * D_IN + d) * H + tid];
        float w1 = Wx[(1 * D_IN + d) * H + tid];
        float w2 = Wx[(2 * D_IN + d) * H + tid];
        float w3 = Wx[(3 * D_IN + d) * H + tid];
        #pragma unroll
        for (int n = 0; n < NT; ++n) {
            float xv = xs[n][d];
            acc0[n] = fmaf(xv, w0, acc0[n]);
            acc1[n] = fmaf(xv, w1, acc1[n]);
            acc2[n] = fmaf(xv, w2, acc2[n]);
            acc3[n] = fmaf(xv, w3, acc3[n]);
        }
    }
    // ---- h_prev @ Wh (128 steps)
    #pragma unroll 2
    for (int k = 0; k < H; ++k) {
        float w0 = Wh[(0 * H + k) * H + tid];
        float w1 = Wh[(1 * H + k) * H + tid];
        float w2 = Wh[(2 * H + k) * H + tid];
        float w3 = Wh[(3 * H + k) * H + tid];
        #pragma unroll
        for (int n = 0; n < NT; ++n) {
            float hv = hs[n][k];
            acc0[n] = fmaf(hv, w0, acc0[n]);
            acc1[n] = fmaf(hv, w1, acc1[n]);
            acc2[n] = fmaf(hv, w2, acc2[n]);
            acc3[n] = fmaf(hv, w3, acc3[n]);
        }
    }

    // ---- peephole LSTM epilogue
    float wc0 = w_c[0 * H + tid];
    float wc1 = w_c[1 * H + tid];
    float wc2 = w_c[2 * H + tid];
    #pragma unroll
    for (int n = 0; n < NT; ++n) {
        size_t off = (size_t)(n0 + n) * H + tid;
        float c  = c_prev[off];
        float ig = sigmoidf_(acc0[n] + wc0 * c);
        float fg = sigmoidf_(acc1[n] + wc1 * c);
        float tg = tanhf(acc2[n]);
        float cn = fg * c + ig * tg;
        float og = sigmoidf_(acc3[n] + wc2 * cn);
        c_new[off] = cn;
        h_new[off] = og * tanhf(cn);
    }
}

// ---------------------------------------------------------------------------
// Kernel B: edge MLP. 256 threads = 4 groups of 64; one edge per group.
// comb (336) staged in smem; hid[j] owned by thread j; W1 stays hot in L1.
// ---------------------------------------------------------------------------
__global__ void __launch_bounds__(256) edge_mlp_kernel(
    const int*   __restrict__ src_ids,       // (B,)
    const int*   __restrict__ dst_ids,       // (B,)
    const int*   __restrict__ etype_ids,     // (B,)
    const float* __restrict__ t_rel,         // (B,1)
    const int*   __restrict__ ecat_codes,    // (2,1000)
    const float* __restrict__ eid_emb,       // (1000,32)
    const float* __restrict__ ecat_emb,      // (2,32,16)
    const float* __restrict__ time_W,        // (1,16)
    const float* __restrict__ time_b,        // (16,)
    const float* __restrict__ W1,            // (336,64)
    const float* __restrict__ b1,            // (64,)
    const float* __restrict__ W2,            // (64,1)
    const float* __restrict__ b2,            // (1,)
    const float* __restrict__ h_new,         // (N,128)
    float* __restrict__ prob)                // (B,)
{
    __shared__ float comb[4][P_IN];
    __shared__ float part[4][2];

    const int tid = threadIdx.x;
    const int g   = tid >> 6;        // group 0..3
    const int j   = tid & 63;        // hidden unit index
    const int b   = blockIdx.x * 4 + g;

    const int   e = etype_ids[b];
    const int   s = src_ids[b];
    const int   d = dst_ids[b];
    const float t = t_rel[b];

    // ---- build comb = [h_src(128), h_dst(128), eid(32), ecat0(16), ecat1(16), time(16)]
    for (int idx = j; idx < P_IN; idx += 64) {
        float v;
        if (idx < 128) {
            v = h_new[(size_t)s * H + idx];
        } else if (idx < 256) {
            v = h_new[(size_t)d * H + (idx - 128)];
        } else if (idx < 288) {
            v = eid_emb[e * 32 + (idx - 256)];
        } else if (idx < 304) {
            int c0 = ecat_codes[e];
            v = ecat_emb[c0 * 16 + (idx - 288)];
        } else if (idx < 320) {
            int c1 = ecat_codes[N_ETYPES + e];
            v = ecat_emb[(32 + c1) * 16 + (idx - 304)];
        } else {
            int k = idx - 320;
            v = fmaf(t, time_W[k], time_b[k]);
        }
        comb[g][idx] = v;
    }
    __syncthreads();

    // ---- hidden layer: hid[j] = relu(b1[j] + comb . W1[:,j])
    float hid = b1[j];
    #pragma unroll 4
    for (int i = 0; i < P_IN; ++i) {
        hid = fmaf(comb[g][i], W1[i * P_HID + j], hid);
    }
    hid = fmaxf(hid, 0.0f);

    // ---- output: sigmoid(sum_j hid[j]*W2[j] + b2)
    float v = hid * W2[j];
    #pragma unroll
    for (int off = 16; off > 0; off >>= 1)
        v += __shfl_down_sync(0xffffffffu, v, off);
    if ((j & 31) == 0) part[g][j >> 5] = v;
    __syncthreads();
    if (j == 0) {
        float zsum = part[g][0] + part[g][1] + b2[0];
        prob[b] = 1.0f / (1.0f + expf(-zsum));
    }
}

// ---------------------------------------------------------------------------
// Input order (metadata.txt / reference signature order):
//  0 src_node_ids  1 dst_node_ids  2 edge_type_ids  3 t_rel
//  4 node_cont     5 node_cat_codes 6 edge_cat_codes 7 edge_index (UNUSED)
//  8 h_prev        9 c_prev        10 node_cat_emb  11 edge_id_emb
// 12 edge_cat_emb 13 time_W        14 time_b        15 Wx
// 16 Wh           17 b_gate        18 w_c           19 W1
// 20 b1           21 W2            22 b2
// Output: [prob(B), h_new(N*H), c_new(N*H)] concatenated.
// ---------------------------------------------------------------------------
extern "C" void kernel_launch(void* const* d_in, const int* in_sizes, int n_in,
                              void* d_out, int out_size)
{
    const int*   src_ids    = (const int*)  d_in[0];
    const int*   dst_ids    = (const int*)  d_in[1];
    const int*   etype_ids  = (const int*)  d_in[2];
    const float* t_rel      = (const float*)d_in[3];
    const float* node_cont  = (const float*)d_in[4];
    const int*   ncat_codes = (const int*)  d_in[5];
    const int*   ecat_codes = (const int*)  d_in[6];
    /* d_in[7] = edge_index, unused */
    const float* h_prev     = (const float*)d_in[8];
    const float* c_prev     = (const float*)d_in[9];
    const float* ncat_emb   = (const float*)d_in[10];
    const float* eid_emb    = (const float*)d_in[11];
    const float* ecat_emb   = (const float*)d_in[12];
    const float* time_W     = (const float*)d_in[13];
    const float* time_b     = (const float*)d_in[14];
    const float* Wx         = (const float*)d_in[15];
    const float* Wh         = (const float*)d_in[16];
    const float* b_gate     = (const float*)d_in[17];
    const float* w_c        = (const float*)d_in[18];
    const float* W1         = (const float*)d_in[19];
    const float* b1         = (const float*)d_in[20];
    const float* W2         = (const float*)d_in[21];
    const float* b2         = (const float*)d_in[22];

    float* out   = (float*)d_out;
    float* prob  = out;
    float* h_new = out + B_EDGES;
    float* c_new = out + B_EDGES + (size_t)N_NODES * H;

    node_update_kernel<<<N_NODES / NT, 128>>>(
        node_cont, ncat_codes, ncat_emb, h_prev, c_prev,
        Wx, Wh, b_gate, w_c, h_new, c_new);

    edge_mlp_kernel<<<B_EDGES / 4, 256>>>(
        src_ids, dst_ids, etype_ids, t_rel,
        ecat_codes, eid_emb, ecat_emb, time_W, time_b,
        W1, b1, W2, b2, h_new, prob);
}

// round 3
// speedup vs baseline: 1.7312x; 1.7312x over previous
#include <cuda_runtime.h>
#include <cuda_bf16.h>
#include <math.h>
#include <stdint.h>

#define N_NODES 150000
#define N_ETYPES 1000
#define B_EDGES 16384
#define H 128
#define P_IN 336
#define P_HID 64

// Node GEMM: z[150000, 512] = A_ext[150000, 576] @ W_ext[576, 512]  (bf16-split)
// K layout: [0,192) hi pass vs W_hi, [192,384) hi pass vs W_lo, [384,576) lo pass vs W_hi
// N layout: n = 4*h + g  (gates interleaved so one N-chunk has all gates for an h-range)
#define KTILES 36              // 576 / 16
#define MTILE 128
#define M_TILES ((N_NODES + MTILE - 1) / MTILE)   // 1172
#define ASTRIDE 392            // padded K stride (bf16 elems): conflict-free ldmatrix
#define SMEM_BYTES (128 * ASTRIDE * 2)            // 100352

// Pre-packed W fragments: [kt(36)][n8(64)][lane(32)*2 regs] as u32 (bf16x2)
__device__ __align__(16) uint32_t g_Wpack[KTILES * 64 * 64];

// ---------------------------------------------------------------------------
__device__ __forceinline__ unsigned short f2bf_bits(float f) {
    return __bfloat16_as_ushort(__float2bfloat16_rn(f));
}
__device__ __forceinline__ float bf_val(unsigned short u) {
    return __bfloat162float(__ushort_as_bfloat16(u));
}
__device__ __forceinline__ float sigmoidf_(float x) { return 1.0f / (1.0f + expf(-x)); }

__device__ __forceinline__ uint32_t smem_u32(const void* p) {
    uint32_t a;
    asm("{ .reg .u64 t; cvta.to.shared.u64 t, %1; cvt.u32.u64 %0, t; }"
        : "=r"(a) : "l"(p));
    return a;
}
__device__ __forceinline__ void ldmatrix_x4(uint32_t* r, uint32_t addr) {
    asm volatile("ldmatrix.sync.aligned.m8n8.x4.shared.b16 {%0,%1,%2,%3}, [%4];"
        : "=r"(r[0]), "=r"(r[1]), "=r"(r[2]), "=r"(r[3]) : "r"(addr));
}
__device__ __forceinline__ void mma16816(float* c, const uint32_t* a, uint2 b) {
    asm volatile("mma.sync.aligned.m16n8k16.row.col.f32.bf16.bf16.f32 "
        "{%0,%1,%2,%3}, {%4,%5,%6,%7}, {%8,%9}, {%0,%1,%2,%3};"
        : "+f"(c[0]), "+f"(c[1]), "+f"(c[2]), "+f"(c[3])
        : "r"(a[0]), "r"(a[1]), "r"(a[2]), "r"(a[3]), "r"(b.x), "r"(b.y));
}

// ---------------------------------------------------------------------------
// Prep: pack W_ext into mma B-fragment order (col-major frag of m16n8k16).
// b0 = {B[k0][n], B[k0+1][n]}, b1 = {B[k0+8][n], B[k0+9][n]}, k0 = kt*16+2*(lane%4)
// ---------------------------------------------------------------------------
__device__ __forceinline__ unsigned short wext_bits(
    int kk, int n, const float* Wx, const float* Wh, const float* bg)
{
    int k; bool want_lo = false;
    if (kk < 192)      k = kk;
    else if (kk < 384) { k = kk - 192; want_lo = true; }
    else               k = kk - 384;
    int g = n & 3, h = n >> 2;
    float w;
    if (k < 128)       w = Wh[(g * 128 + k) * 128 + h];
    else if (k < 178)  w = Wx[(g * 50 + (k - 128)) * 128 + h];
    else if (k == 178) w = bg[g * 128 + h];
    else               w = 0.0f;
    unsigned short hi = f2bf_bits(w);
    if (!want_lo) return hi;
    return f2bf_bits(w - bf_val(hi));
}

__global__ void prep_weights_kernel(const float* __restrict__ Wx,
                                    const float* __restrict__ Wh,
                                    const float* __restrict__ bg)
{
    int idx = blockIdx.x * blockDim.x + threadIdx.x;
    if (idx >= KTILES * 64 * 64) return;
    int r    = idx & 63;          // lane*2 + reg
    int lane = r >> 1, reg = r & 1;
    int blk  = idx >> 6;          // kt*64 + n8
    int kt   = blk >> 6, n8 = blk & 63;
    int n    = n8 * 8 + (lane >> 2);
    int kk0  = kt * 16 + (lane & 3) * 2 + reg * 8;
    unsigned short u0 = wext_bits(kk0,     n, Wx, Wh, bg);
    unsigned short u1 = wext_bits(kk0 + 1, n, Wx, Wh, bg);
    g_Wpack[idx] = (uint32_t)u0 | ((uint32_t)u1 << 16);
}

// ---------------------------------------------------------------------------
// Node update: bf16-split mma.sync GEMM + fused peephole LSTM.
// 512 threads = 16 warps (4m x 4n), CTA tile 128 nodes x 256 cols (= 64 h).
// gridDim.x = M_TILES*2; blockIdx.x = mtile*2 + chunk.
// ---------------------------------------------------------------------------
__global__ void __launch_bounds__(512, 1) node_update_mma_kernel(
    const float* __restrict__ node_cont,   // (N,2)
    const int*   __restrict__ ncat_codes,  // (3,N)
    const float* __restrict__ ncat_emb,    // (3,64,16)
    const float* __restrict__ h_prev,      // (N,128)
    const float* __restrict__ c_prev,      // (N,128)
    const float* __restrict__ w_c,         // (3,128)
    float* __restrict__ h_new,
    float* __restrict__ c_new)
{
    extern __shared__ __align__(16) unsigned char smraw[];
    __nv_bfloat16* As  = (__nv_bfloat16*)smraw;   // [128][ASTRIDE]
    float*         zsm = (float*)smraw;           // reused post-GEMM: [64][256]

    const int tid  = threadIdx.x;
    const int lane = tid & 31;
    const int wid  = tid >> 5;
    const int wm   = wid & 3;            // warp m index (0..3)
    const int wn   = wid >> 2;           // warp n index (0..3)
    const int mtile = blockIdx.x >> 1;
    const int chunk = blockIdx.x & 1;    // which 256-col (=64 h) chunk
    const int n0m   = mtile * MTILE;

    // ---- A build: hi cols [0,192), lo cols [192,384)
    // vector phase: k in [0,128) = h_prev (8 bf16 per uint4 store)
    #pragma unroll
    for (int it = 0; it < 4; ++it) {
        int cid = tid + it * 512;            // 2048 chunks of 8
        int row = cid >> 4, kb = (cid & 15) << 3;
        int node = n0m + row;
        float f[8];
        if (node < N_NODES) {
            const float4* hp = (const float4*)(h_prev + (size_t)node * H + kb);
            float4 a = hp[0], b = hp[1];
            f[0]=a.x; f[1]=a.y; f[2]=a.z; f[3]=a.w;
            f[4]=b.x; f[5]=b.y; f[6]=b.z; f[7]=b.w;
        } else {
            #pragma unroll
            for (int q = 0; q < 8; ++q) f[q] = 0.0f;
        }
        uint32_t hw[4], lw[4];
        #pragma unroll
        for (int q = 0; q < 4; ++q) {
            unsigned short h0 = f2bf_bits(f[2*q]),   h1 = f2bf_bits(f[2*q+1]);
            unsigned short l0 = f2bf_bits(f[2*q]   - bf_val(h0));
            unsigned short l1 = f2bf_bits(f[2*q+1] - bf_val(h1));
            hw[q] = (uint32_t)h0 | ((uint32_t)h1 << 16);
            lw[q] = (uint32_t)l0 | ((uint32_t)l1 << 16);
        }
        *(uint4*)&As[row * ASTRIDE + kb]       = make_uint4(hw[0], hw[1], hw[2], hw[3]);
        *(uint4*)&As[row * ASTRIDE + 192 + kb] = make_uint4(lw[0], lw[1], lw[2], lw[3]);
    }
    // scalar phase: k in [128,192) = x-feats(2+48) + bias(1) + zero pad
    #pragma unroll 2
    for (int it = 0; it < 16; ++it) {
        int e = tid + it * 512;              // 8192 elements
        int row = e >> 6, kr = e & 63;
        int node = n0m + row;
        float v = 0.0f;
        if (node < N_NODES) {
            if (kr < 2)        v = node_cont[node * 2 + kr];
            else if (kr < 50)  {
                int j = (kr - 2) >> 4, kd = (kr - 2) & 15;
                int code = ncat_codes[j * N_NODES + node];
                v = ncat_emb[(j * 64 + code) * 16 + kd];
            } else if (kr == 50) v = 1.0f;   // bias row
        }
        unsigned short hi = f2bf_bits(v);
        As[row * ASTRIDE + 128 + kr] = __ushort_as_bfloat16(hi);
        As[row * ASTRIDE + 320 + kr] = __ushort_as_bfloat16(f2bf_bits(v - bf_val(hi)));
    }
    __syncthreads();

    // ---- GEMM mainloop
    float acc[2][8][4];
    #pragma unroll
    for (int mt = 0; mt < 2; ++mt)
        #pragma unroll
        for (int nt = 0; nt < 8; ++nt)
            #pragma unroll
            for (int q = 0; q < 4; ++q) acc[mt][nt][q] = 0.0f;

    const uint32_t as_base = smem_u32(As);
    const uint32_t* __restrict__ wp_base =
        g_Wpack + (size_t)(chunk * 32 + wn * 8) * 64 + lane * 2;

    #pragma unroll 2
    for (int kt = 0; kt < KTILES; ++kt) {
        int acol = (kt < 12) ? kt * 16
                 : (kt < 24) ? (kt - 12) * 16
                 : 192 + (kt - 24) * 16;
        uint32_t a[2][4];
        #pragma unroll
        for (int mt = 0; mt < 2; ++mt) {
            uint32_t addr = as_base +
                ((uint32_t)(wm * 32 + mt * 16 + (lane & 15)) * ASTRIDE
                 + acol + (lane >> 4) * 8) * 2;
            ldmatrix_x4(a[mt], addr);
        }
        uint2 b[8];
        const uint32_t* wp = wp_base + kt * 4096;   // 64 n8 * 64 u32
        #pragma unroll
        for (int nt = 0; nt < 8; ++nt) b[nt] = *(const uint2*)(wp + nt * 64);
        #pragma unroll
        for (int nt = 0; nt < 8; ++nt) {
            mma16816(acc[0][nt], a[0], b[nt]);
            mma16816(acc[1][nt], a[1], b[nt]);
        }
    }

    // ---- epilogue: two 64-node halves through smem, then fused LSTM
    const int group = lane >> 2;
    const int qq    = lane & 3;
    #pragma unroll
    for (int half = 0; half < 2; ++half) {
        __syncthreads();
        if ((wm >> 1) == half) {
            int rbase = (wm & 1) * 32;
            #pragma unroll
            for (int mt = 0; mt < 2; ++mt) {
                int r = rbase + mt * 16 + group;
                #pragma unroll
                for (int nt = 0; nt < 8; ++nt) {
                    int l = wn * 64 + nt * 8 + qq * 2;
                    *(float2*)&zsm[r * 256 + l] =
                        make_float2(acc[mt][nt][0], acc[mt][nt][1]);
                    *(float2*)&zsm[(r + 8) * 256 + l] =
                        make_float2(acc[mt][nt][2], acc[mt][nt][3]);
                }
            }
        }
        __syncthreads();
        #pragma unroll
        for (int i = 0; i < 8; ++i) {
            int cell = tid + i * 512;         // 4096 = 64 nodes x 64 h
            int nl = cell >> 6, hl = cell & 63;
            int node = n0m + half * 64 + nl;
            if (node < N_NODES) {
                int h = chunk * 64 + hl;
                float4 z = *(const float4*)&zsm[nl * 256 + hl * 4]; // g0..g3
                size_t off = (size_t)node * H + h;
                float cv = c_prev[off];
                float ig = sigmoidf_(z.x + w_c[h] * cv);
                float fg = sigmoidf_(z.y + w_c[128 + h] * cv);
                float tg = tanhf(z.z);
                float cn = fg * cv + ig * tg;
                float og = sigmoidf_(z.w + w_c[256 + h] * cn);
                c_new[off] = cn;
                h_new[off] = og * tanhf(cn);
            }
        }
    }
}

// ---------------------------------------------------------------------------
// Edge MLP (unchanged: ~92us, not the bottleneck)
// ---------------------------------------------------------------------------
__global__ void __launch_bounds__(256) edge_mlp_kernel(
    const int*   __restrict__ src_ids, const int* __restrict__ dst_ids,
    const int*   __restrict__ etype_ids, const float* __restrict__ t_rel,
    const int*   __restrict__ ecat_codes, const float* __restrict__ eid_emb,
    const float* __restrict__ ecat_emb, const float* __restrict__ time_W,
    const float* __restrict__ time_b, const float* __restrict__ W1,
    const float* __restrict__ b1, const float* __restrict__ W2,
    const float* __restrict__ b2, const float* __restrict__ h_new,
    float* __restrict__ prob)
{
    __shared__ float comb[4][P_IN];
    __shared__ float part[4][2];

    const int tid = threadIdx.x;
    const int g   = tid >> 6;
    const int j   = tid & 63;
    const int b   = blockIdx.x * 4 + g;

    const int   e = etype_ids[b];
    const int   s = src_ids[b];
    const int   d = dst_ids[b];
    const float t = t_rel[b];

    for (int idx = j; idx < P_IN; idx += 64) {
        float v;
        if (idx < 128)       v = h_new[(size_t)s * H + idx];
        else if (idx < 256)  v = h_new[(size_t)d * H + (idx - 128)];
        else if (idx < 288)  v = eid_emb[e * 32 + (idx - 256)];
        else if (idx < 304)  { int c0 = ecat_codes[e];
                               v = ecat_emb[c0 * 16 + (idx - 288)]; }
        else if (idx < 320)  { int c1 = ecat_codes[N_ETYPES + e];
                               v = ecat_emb[(32 + c1) * 16 + (idx - 304)]; }
        else                 { int k = idx - 320;
                               v = fmaf(t, time_W[k], time_b[k]); }
        comb[g][idx] = v;
    }
    __syncthreads();

    float hid = b1[j];
    #pragma unroll 4
    for (int i = 0; i < P_IN; ++i)
        hid = fmaf(comb[g][i], W1[i * P_HID + j], hid);
    hid = fmaxf(hid, 0.0f);

    float v = hid * W2[j];
    #pragma unroll
    for (int off = 16; off > 0; off >>= 1)
        v += __shfl_down_sync(0xffffffffu, v, off);
    if ((j & 31) == 0) part[g][j >> 5] = v;
    __syncthreads();
    if (j == 0)
        prob[b] = 1.0f / (1.0f + expf(-(part[g][0] + part[g][1] + b2[0])));
}

// ---------------------------------------------------------------------------
extern "C" void kernel_launch(void* const* d_in, const int* in_sizes, int n_in,
                              void* d_out, int out_size)
{
    const int*   src_ids    = (const int*)  d_in[0];
    const int*   dst_ids    = (const int*)  d_in[1];
    const int*   etype_ids  = (const int*)  d_in[2];
    const float* t_rel      = (const float*)d_in[3];
    const float* node_cont  = (const float*)d_in[4];
    const int*   ncat_codes = (const int*)  d_in[5];
    const int*   ecat_codes = (const int*)  d_in[6];
    /* d_in[7] = edge_index, unused */
    const float* h_prev     = (const float*)d_in[8];
    const float* c_prev     = (const float*)d_in[9];
    const float* ncat_emb   = (const float*)d_in[10];
    const float* eid_emb    = (const float*)d_in[11];
    const float* ecat_emb   = (const float*)d_in[12];
    const float* time_W     = (const float*)d_in[13];
    const float* time_b     = (const float*)d_in[14];
    const float* Wx         = (const float*)d_in[15];
    const float* Wh         = (const float*)d_in[16];
    const float* b_gate     = (const float*)d_in[17];
    const float* w_c        = (const float*)d_in[18];
    const float* W1         = (const float*)d_in[19];
    const float* b1         = (const float*)d_in[20];
    const float* W2         = (const float*)d_in[21];
    const float* b2         = (const float*)d_in[22];

    float* out   = (float*)d_out;
    float* prob  = out;
    float* h_new = out + B_EDGES;
    float* c_new = out + B_EDGES + (size_t)N_NODES * H;

    static int smem_set = 0;
    if (!smem_set) {
        cudaFuncSetAttribute(node_update_mma_kernel,
                             cudaFuncAttributeMaxDynamicSharedMemorySize, SMEM_BYTES);
        smem_set = 1;
    }

    prep_weights_kernel<<<(KTILES * 64 * 64 + 255) / 256, 256>>>(Wx, Wh, b_gate);

    node_update_mma_kernel<<<M_TILES * 2, 512, SMEM_BYTES>>>(
        node_cont, ncat_codes, ncat_emb, h_prev, c_prev, w_c, h_new, c_new);

    edge_mlp_kernel<<<B_EDGES / 4, 256>>>(
        src_ids, dst_ids, etype_ids, t_rel,
        ecat_codes, eid_emb, ecat_emb, time_W, time_b,
        W1, b1, W2, b2, h_new, prob);
}